// round 3
// baseline (speedup 1.0000x reference)
#include <cuda_runtime.h>
#include <cub/cub.cuh>

#define KA    9
#define HH    240
#define WW    240
#define HW    57600          // HH*WW
#define NTOT  518400         // KA*HW
#define WK    2160           // WW*KA
#define PRE   6000
#define POST  300
#define CAP   8192
#define NB    65536
#define WORDS 188            // ceil(PRE/32)
#define NTHR  1024
#define MAXBLK 148

__device__ unsigned            g_keys[NTOT];
__device__ unsigned            g_hist[NB];
__device__ unsigned            g_cnt;
__device__ int                 g_bound;
__device__ unsigned long long  g_cand[CAP];
__device__ int                 g_order[PRE];
__device__ float               g_sc[PRE];
__device__ float4              g_boxes[PRE];
__device__ unsigned            g_bar_cnt;   // zero-initialized, self-resetting
__device__ unsigned            g_bar_gen;   // monotone generation counter

typedef cub::BlockRadixSort<unsigned long long, NTHR, 8> Sorter;

__device__ __forceinline__ unsigned mono(float f) {
    unsigned b = __float_as_uint(f);
    return (b & 0x80000000u) ? ~b : (b | 0x80000000u);
}
__device__ __forceinline__ float unmono(unsigned m) {
    unsigned b = (m & 0x80000000u) ? (m ^ 0x80000000u) : ~m;
    return __uint_as_float(b);
}

// software grid barrier — safe because grid <= #SMs and smem/threads force
// every block resident in wave 1 (capacity >= grid).
__device__ __forceinline__ void gsync(int nb) {
    __syncthreads();
    if (threadIdx.x == 0) {
        __threadfence();
        unsigned gen = *((volatile unsigned*)&g_bar_gen);   // read BEFORE arriving
        unsigned t = atomicAdd(&g_bar_cnt, 1u);
        if (t == (unsigned)(nb - 1)) {
            atomicExch(&g_bar_cnt, 0u);
            __threadfence();
            atomicAdd(&g_bar_gen, 1u);                      // release
        } else {
            while (*((volatile unsigned*)&g_bar_gen) == gen) __nanosleep(64);
            __threadfence();                                // acquire
        }
    }
    __syncthreads();
}

__global__ __launch_bounds__(NTHR, 1)
void k_fused(const float* __restrict__ cls,
             const float* __restrict__ deltas,
             const float* __restrict__ anchors,
             float* __restrict__ out, int nb) {
    extern __shared__ char smraw[];
    const int tid = threadIdx.x;
    const int bid = blockIdx.x;
    const int gt  = bid * NTHR + tid;
    const int gs  = nb * NTHR;

    // ---- P0: zero histogram + counter -----------------------------------
    for (int i = gt; i < NB; i += gs) g_hist[i] = 0u;
    if (gt == 0) g_cnt = 0u;
    gsync(nb);

    // ---- P1: scores -> monotone keys + 64K-bucket histogram -------------
    for (int i = gt; i < NTOT; i += gs) {
        int k = i / HW;
        int r = i - k * HW;
        float s = __ldg(&cls[(2 * k) * HW + r]);     // even (positive) channel
        unsigned key = mono(s);
        g_keys[i] = key;
        atomicAdd(&g_hist[key >> 16], 1u);
    }
    gsync(nb);

    // ---- P2: boundary bucket of rank PRE (block 0 only) -----------------
    if (bid == 0) {
        __shared__ int ps[NTHR];
        int base = tid * 64;
        int sum = 0;
        #pragma unroll 8
        for (int j = 0; j < 64; ++j) sum += (int)__ldcg(&g_hist[base + j]);
        ps[tid] = sum;
        __syncthreads();
        for (int d = 1; d < NTHR; d <<= 1) {        // inclusive suffix scan
            int v = (tid + d < NTHR) ? ps[tid + d] : 0;
            __syncthreads();
            ps[tid] += v;
            __syncthreads();
        }
        int St  = ps[tid];
        int St1 = (tid + 1 < NTHR) ? ps[tid + 1] : 0;
        if (St >= PRE && St1 < PRE) {
            int running = St1;
            int B = base;
            for (int j = 63; j >= 0; --j) {
                running += (int)__ldcg(&g_hist[base + j]);
                if (running >= PRE) { B = base + j; break; }
            }
            g_bound = B;
        }
    }
    gsync(nb);

    // ---- P3: compact candidates >= bound --------------------------------
    const int bound = __ldcg(&g_bound);
    for (int i = gt; i < NTOT; i += gs) {
        unsigned key = __ldcg(&g_keys[i]);
        if ((int)(key >> 16) >= bound) {
            unsigned pos = atomicAdd(&g_cnt, 1u);
            if (pos < CAP)
                g_cand[pos] = ((unsigned long long)key << 20)
                            | (unsigned)((~(unsigned)i) & 0xFFFFFu);
        }
    }
    gsync(nb);

    // ---- P4: block-0 cub radix sort (desc) of up to 8192 52-bit keys ----
    if (bid == 0) {
        Sorter::TempStorage& ts = *reinterpret_cast<Sorter::TempStorage*>(smraw);
        unsigned n = __ldcg(&g_cnt);
        if (n > CAP) n = CAP;
        unsigned long long keys[8];
        #pragma unroll
        for (int it = 0; it < 8; ++it) {
            int e = tid * 8 + it;
            keys[it] = (e < (int)n) ? __ldcg(&g_cand[e]) : 0ULL;
        }
        Sorter(ts).SortDescending(keys, 0, 52);
        #pragma unroll
        for (int it = 0; it < 8; ++it) {
            int p = tid * 8 + it;
            if (p < PRE) {
                unsigned long long v = keys[it];
                g_order[p] = (int)((~(unsigned)v) & 0xFFFFFu);
                g_sc[p]    = unmono((unsigned)(v >> 20));
            }
        }
    }
    gsync(nb);

    // ---- P5: grid-wide gather of clipped boxes (torch-faithful layout) --
    for (int p = gt; p < PRE; p += gs) {
        int i  = __ldcg(&g_order[p]);
        int hp = i / WK;
        int t  = i - hp * WK;
        int wp = t / KA;
        int kp = t - wp * KA;
        float v[4];
        #pragma unroll
        for (int j = 0; j < 4; ++j) {
            int F   = ((kp * 4 + j) * HH + hp) * WW + wp;
            int j2  = F & 3;
            int F4  = F >> 2;
            int k2  = F4 % KA;
            int rem = F4 / KA;
            int w2  = rem % WW;
            int h2  = rem / WW;
            float a = __ldg(&anchors[((h2 * WW + w2) * KA + k2) * 4 + j2]);
            float d = __ldg(&deltas[(k2 * 4 + j2) * HW + h2 * WW + w2]);
            v[j] = fminf(fmaxf(a + d, 0.0f), 1920.0f);
        }
        g_boxes[p] = make_float4(v[0], v[1], v[2], v[3]);
    }
    gsync(nb);

    // ---- P6: block-0 bitmask NMS + output -------------------------------
    if (bid == 0) {
        float4* bx = (float4*)smraw;
        __shared__ unsigned supw[WORDS];
        __shared__ int kept[POST];
        int warp = tid >> 5, lane = tid & 31;

        for (int p = tid; p < PRE; p += NTHR) bx[p] = __ldcg(&g_boxes[p]);
        if (tid < WORDS) supw[tid] = (tid == WORDS - 1) ? 0xFFFF0000u : 0u;
        __syncthreads();

        int nk = 0, i = 0;
        while (true) {
            int wi = i >> 5;
            unsigned w = supw[wi] | ((1u << (i & 31)) - 1u);
            while (w == 0xFFFFFFFFu && ++wi < WORDS) w = supw[wi];
            if (w == 0xFFFFFFFFu) break;
            i = (wi << 5) + (__ffs(~w) - 1);
            if (tid == 0) kept[nk] = i;
            ++nk;
            if (nk >= POST) break;

            float4 bi = bx[i];
            float aw = fmaxf(bi.z - bi.x, 0.0f);
            float ah = fmaxf(bi.w - bi.y, 0.0f);
            float area_i = __fmul_rn(aw, ah);

            int w0 = (i + 1) >> 5;
            for (int wd = w0 + warp; wd < WORDS; wd += 32) {
                unsigned cur = supw[wd];
                if (cur != 0xFFFFFFFFu) {
                    int j = (wd << 5) + lane;
                    bool sup = false;
                    if (j > i && !((cur >> lane) & 1u)) {
                        float4 bj = bx[j];
                        float lx = fmaxf(bi.x, bj.x);
                        float ly = fmaxf(bi.y, bj.y);
                        float rx = fminf(bi.z, bj.z);
                        float ry = fminf(bi.w, bj.w);
                        float iw = fmaxf(rx - lx, 0.0f);
                        float ih = fmaxf(ry - ly, 0.0f);
                        float inter  = __fmul_rn(iw, ih);
                        float bw = fmaxf(bj.z - bj.x, 0.0f);
                        float bh = fmaxf(bj.w - bj.y, 0.0f);
                        float area_j = __fmul_rn(bw, bh);
                        float uni = fmaxf(__fsub_rn(__fadd_rn(area_i, area_j), inter), 1e-9f);
                        sup = (__fdiv_rn(inter, uni) > 0.6f);
                    }
                    unsigned nb2 = __ballot_sync(0xFFFFFFFFu, sup);
                    if (lane == 0 && nb2) supw[wd] = cur | nb2;
                }
            }
            ++i;
            __syncthreads();
        }
        __syncthreads();

        for (int p = tid; p < POST; p += NTHR) {
            int q = (p < nk) ? kept[p] : 0;
            float4 b = bx[q];
            out[p * 5 + 0] = g_sc[q];
            out[p * 5 + 1] = b.x;
            out[p * 5 + 2] = b.y;
            out[p * 5 + 3] = b.z;
            out[p * 5 + 4] = b.w;
        }
    }
}

// ---------------------------------------------------------------- launcher
extern "C" void kernel_launch(void* const* d_in, const int* in_sizes, int n_in,
                              void* d_out, int out_size) {
    const float* cls     = (const float*)d_in[0];  // [1, 2K, H, W]
    const float* deltas  = (const float*)d_in[1];  // [1, 4K, H, W]
    const float* anchors = (const float*)d_in[2];  // [H, W, K, 4]
    float* out = (float*)d_out;                    // [1, POST, 5]

    int smCount = MAXBLK;
    cudaDeviceGetAttribute(&smCount, cudaDevAttrMultiProcessorCount, 0);
    int nb = smCount < MAXBLK ? smCount : MAXBLK;

    size_t dsz = sizeof(Sorter::TempStorage);
    if (dsz < (size_t)PRE * sizeof(float4)) dsz = (size_t)PRE * sizeof(float4);

    cudaFuncSetAttribute(k_fused, cudaFuncAttributeMaxDynamicSharedMemorySize, (int)dsz);
    k_fused<<<nb, NTHR, dsz>>>(cls, deltas, anchors, out, nb);
}

// round 5
// speedup vs baseline: 3.7404x; 3.7404x over previous
#include <cuda_runtime.h>
#include <cub/cub.cuh>

#define KA    9
#define HH    240
#define WW    240
#define HW    57600          // HH*WW
#define NTOT  518400         // KA*HW
#define WK    2160           // WW*KA
#define PRE   6000
#define POST  300
#define CAP   8192
#define NB    65536
#define NTHR  1024
#define MAXBLK 148

__device__ unsigned            g_hist[NB];    // zero at load; re-zeroed after use each launch
__device__ unsigned            g_cnt;         // zero at load; reset (safely) each launch
__device__ int                 g_bound;
__device__ unsigned long long  g_cand[CAP];
__device__ int                 g_order[PRE];
__device__ float               g_sc[PRE];
__device__ float4              g_boxes[PRE];
__device__ unsigned            g_bar_cnt;     // self-resetting
__device__ unsigned            g_bar_gen;     // monotone

typedef cub::BlockRadixSort<unsigned long long, NTHR, 8> Sorter;

__device__ __forceinline__ unsigned mono(float f) {
    unsigned b = __float_as_uint(f);
    return (b & 0x80000000u) ? ~b : (b | 0x80000000u);
}
__device__ __forceinline__ float unmono(unsigned m) {
    unsigned b = (m & 0x80000000u) ? (m ^ 0x80000000u) : ~m;
    return __uint_as_float(b);
}
__device__ __forceinline__ float box_area(float4 b) {
    return __fmul_rn(fmaxf(b.z - b.x, 0.0f), fmaxf(b.w - b.y, 0.0f));
}
// exact op-for-op match with the formula that produced rel_err 0.0
__device__ __forceinline__ bool iou_gt(float4 a, float areaA, float4 b, float areaB) {
    float lx = fmaxf(a.x, b.x);
    float ly = fmaxf(a.y, b.y);
    float rx = fminf(a.z, b.z);
    float ry = fminf(a.w, b.w);
    float iw = fmaxf(rx - lx, 0.0f);
    float ih = fmaxf(ry - ly, 0.0f);
    float inter = __fmul_rn(iw, ih);
    float uni = fmaxf(__fsub_rn(__fadd_rn(areaA, areaB), inter), 1e-9f);
    return __fdiv_rn(inter, uni) > 0.6f;
}

// software grid barrier — grid <= #SMs and 1 block/SM (smem) force wave-1 residency
__device__ __forceinline__ void gsync(int nb) {
    __syncthreads();
    if (threadIdx.x == 0) {
        __threadfence();
        unsigned gen = *((volatile unsigned*)&g_bar_gen);
        unsigned t = atomicAdd(&g_bar_cnt, 1u);
        if (t == (unsigned)(nb - 1)) {
            atomicExch(&g_bar_cnt, 0u);
            __threadfence();
            atomicAdd(&g_bar_gen, 1u);
        } else {
            while (*((volatile unsigned*)&g_bar_gen) == gen) __nanosleep(64);
            __threadfence();
        }
    }
    __syncthreads();
}

__global__ __launch_bounds__(NTHR, 1)
void k_fused(const float* __restrict__ cls,
             const float* __restrict__ deltas,
             const float* __restrict__ anchors,
             float* __restrict__ out, int nb) {
    extern __shared__ char smraw[];
    const int tid = threadIdx.x;
    const int bid = blockIdx.x;
    const int gt  = bid * NTHR + tid;
    const int gs  = nb * NTHR;

    // ---- P1: scores -> 64K-bucket histogram (hist pre-zeroed invariant) ----
    for (int i = gt; i < NTOT; i += gs) {
        int k = i / HW;
        int r = i - k * HW;
        float s = __ldg(&cls[(2 * k) * HW + r]);
        atomicAdd(&g_hist[mono(s) >> 16], 1u);
    }
    gsync(nb);

    // ---- P2: boundary bucket of rank PRE (block 0) ----------------------
    if (bid == 0) {
        __shared__ int ps[NTHR];
        const uint4* h4 = (const uint4*)g_hist;
        int base4 = tid * 16;                    // 16 uint4 = 64 buckets
        int sum = 0;
        #pragma unroll
        for (int j = 0; j < 16; ++j) {
            uint4 v = __ldcg(&h4[base4 + j]);
            sum += (int)(v.x + v.y + v.z + v.w);
        }
        ps[tid] = sum;
        __syncthreads();
        for (int d = 1; d < NTHR; d <<= 1) {     // inclusive suffix scan
            int v = (tid + d < NTHR) ? ps[tid + d] : 0;
            __syncthreads();
            ps[tid] += v;
            __syncthreads();
        }
        int St  = ps[tid];
        int St1 = (tid + 1 < NTHR) ? ps[tid + 1] : 0;
        if (St >= PRE && St1 < PRE) {
            int running = St1;
            int base = tid * 64;
            int B = base;
            for (int j = 63; j >= 0; --j) {
                running += (int)__ldcg(&g_hist[base + j]);
                if (running >= PRE) { B = base + j; break; }
            }
            g_bound = B;
        }
    }
    gsync(nb);

    // ---- P3: recompute keys, compact candidates >= bound ----------------
    {
        const int bound = __ldcg(&g_bound);
        for (int i = gt; i < NTOT; i += gs) {
            int k = i / HW;
            int r = i - k * HW;
            float s = __ldg(&cls[(2 * k) * HW + r]);
            unsigned key = mono(s);
            if ((int)(key >> 16) >= bound) {
                unsigned pos = atomicAdd(&g_cnt, 1u);
                if (pos < CAP)
                    g_cand[pos] = ((unsigned long long)key << 20)
                                | (unsigned)((~(unsigned)i) & 0xFFFFFu);
            }
        }
    }
    gsync(nb);

    // ---- P4: block-0 cub radix sort; other blocks re-zero hist ----------
    if (bid == 0) {
        __shared__ unsigned sh_n;                // RACE FIX: broadcast before reset
        if (tid == 0) { sh_n = g_cnt; g_cnt = 0u; }
        __syncthreads();
        unsigned n = sh_n;
        if (n > CAP) n = CAP;

        Sorter::TempStorage& ts = *reinterpret_cast<Sorter::TempStorage*>(smraw);
        unsigned long long keys[8];
        #pragma unroll
        for (int it = 0; it < 8; ++it) {
            int e = tid * 8 + it;
            keys[it] = (e < (int)n) ? __ldcg(&g_cand[e]) : 0ULL;
        }
        Sorter(ts).SortDescending(keys, 0, 52);
        #pragma unroll
        for (int it = 0; it < 8; ++it) {
            int p = tid * 8 + it;
            if (p < PRE) {
                unsigned long long v = keys[it];
                g_order[p] = (int)((~(unsigned)v) & 0xFFFFFu);
                g_sc[p]    = unmono((unsigned)(v >> 20));
            }
        }
    } else {
        // hist dead after P3 -> restore zero invariant for next launch
        int gt2 = (bid - 1) * NTHR + tid;
        int gs2 = (nb - 1) * NTHR;
        for (int i = gt2; i < NB; i += gs2) g_hist[i] = 0u;
    }
    gsync(nb);

    // ---- P5: grid-wide gather of clipped boxes (torch-faithful layout) --
    for (int p = gt; p < PRE; p += gs) {
        int i  = __ldcg(&g_order[p]);
        int hp = i / WK;
        int t  = i - hp * WK;
        int wp = t / KA;
        int kp = t - wp * KA;
        float v[4];
        #pragma unroll
        for (int j = 0; j < 4; ++j) {
            int F   = ((kp * 4 + j) * HH + hp) * WW + wp;
            int j2  = F & 3;
            int F4  = F >> 2;
            int k2  = F4 % KA;
            int rem = F4 / KA;
            int w2  = rem % WW;
            int h2  = rem / WW;
            float a = __ldg(&anchors[((h2 * WW + w2) * KA + k2) * 4 + j2]);
            float d = __ldg(&deltas[(k2 * 4 + j2) * HW + h2 * WW + w2]);
            v[j] = fminf(fmaxf(a + d, 0.0f), 1920.0f);
        }
        g_boxes[p] = make_float4(v[0], v[1], v[2], v[3]);
    }
    gsync(nb);

    // ---- P6: block-0 LAZY BATCHED NMS + output --------------------------
    if (bid == 0) {
        float4* bx = (float4*)smraw;             // PRE float4 = 96000 B
        __shared__ float4   kbox[POST];
        __shared__ float    karea[POST];
        __shared__ int      kidx[POST];
        __shared__ int      s_nk;
        __shared__ unsigned s_sup;

        for (int p = tid; p < PRE; p += NTHR) bx[p] = __ldcg(&g_boxes[p]);
        if (tid == 0) { s_nk = 0; s_sup = 0u; }
        __syncthreads();

        for (int base = 0; base < PRE; base += 32) {
            // phase 1: test 32 batch candidates vs all currently-kept boxes
            int nk = s_nk;
            int total = nk << 5;                 // nk * 32
            for (int idx = tid; idx < total; idx += NTHR) {
                int c = idx & 31;
                if (base + c < PRE) {
                    float4 bj = bx[base + c];
                    float  aj = box_area(bj);
                    int k = idx >> 5;
                    if (iou_gt(kbox[k], karea[k], bj, aj))
                        atomicOr(&s_sup, 1u << c);
                }
            }
            __syncthreads();

            // phase 2: one warp serially resolves survivors within the batch
            if (tid < 32) {
                int lane = tid;
                int rem  = PRE - base;
                unsigned valid = (rem >= 32) ? 0xFFFFFFFFu : ((1u << rem) - 1u);
                unsigned alive = (~s_sup) & valid;
                int myj = base + ((lane < rem) ? lane : 0);
                float4 myb = bx[myj];
                float  mya = box_area(myb);
                int nk2 = s_nk;
                while (alive && nk2 < POST) {
                    int l = __ffs((int)alive) - 1;
                    alive &= ~(1u << l);
                    float4 kb;
                    kb.x = __shfl_sync(0xFFFFFFFFu, myb.x, l);
                    kb.y = __shfl_sync(0xFFFFFFFFu, myb.y, l);
                    kb.z = __shfl_sync(0xFFFFFFFFu, myb.z, l);
                    kb.w = __shfl_sync(0xFFFFFFFFu, myb.w, l);
                    float ka_ = __shfl_sync(0xFFFFFFFFu, mya, l);
                    if (lane == 0) { kbox[nk2] = kb; karea[nk2] = ka_; kidx[nk2] = base + l; }
                    ++nk2;
                    if (nk2 >= POST) break;
                    bool sup = false;
                    if (alive & (1u << lane)) sup = iou_gt(kb, ka_, myb, mya);
                    alive &= ~__ballot_sync(0xFFFFFFFFu, sup);
                }
                if (lane == 0) { s_nk = nk2; s_sup = 0u; }
            }
            __syncthreads();
            if (s_nk >= POST) break;
        }

        int nk = s_nk;
        // output [1, POST, 5]; nonzero(..., fill_value=0) -> pad with candidate 0
        for (int p = tid; p < POST; p += NTHR) {
            int q = (p < nk) ? kidx[p] : 0;
            float4 b = bx[q];
            out[p * 5 + 0] = g_sc[q];
            out[p * 5 + 1] = b.x;
            out[p * 5 + 2] = b.y;
            out[p * 5 + 3] = b.z;
            out[p * 5 + 4] = b.w;
        }
    }
}

// ---------------------------------------------------------------- launcher
extern "C" void kernel_launch(void* const* d_in, const int* in_sizes, int n_in,
                              void* d_out, int out_size) {
    const float* cls     = (const float*)d_in[0];  // [1, 2K, H, W]
    const float* deltas  = (const float*)d_in[1];  // [1, 4K, H, W]
    const float* anchors = (const float*)d_in[2];  // [H, W, K, 4]
    float* out = (float*)d_out;                    // [1, POST, 5]

    int smCount = MAXBLK;
    cudaDeviceGetAttribute(&smCount, cudaDevAttrMultiProcessorCount, 0);
    int nb = smCount < MAXBLK ? smCount : MAXBLK;

    size_t dsz = sizeof(Sorter::TempStorage);
    if (dsz < (size_t)PRE * sizeof(float4)) dsz = (size_t)PRE * sizeof(float4);

    cudaFuncSetAttribute(k_fused, cudaFuncAttributeMaxDynamicSharedMemorySize, (int)dsz);
    k_fused<<<nb, NTHR, dsz>>>(cls, deltas, anchors, out, nb);
}

// round 6
// speedup vs baseline: 4.1788x; 1.1172x over previous
#include <cuda_runtime.h>

#define KA    9
#define HH    240
#define WW    240
#define HW    57600          // HH*WW
#define NTOT  518400         // KA*HW
#define WK    2160           // WW*KA
#define PRE   6000
#define POST  300
#define CAP   8192
#define NB    65536
#define NTHR  1024
#define MAXBLK 148
#define GRP   16             // candidate groups (GRP*512 = CAP)
#define CHK   9              // key chunks; GRP*CHK = 144 work tiles

__device__ unsigned            g_hist[NB];    // zero invariant (restored each launch)
__device__ unsigned            g_cnt;         // zero invariant
__device__ unsigned            g_rank[CAP];   // zero invariant
__device__ int                 g_bound;
__device__ unsigned long long  g_cand[CAP];
__device__ float               g_sc[PRE];
__device__ float4              g_boxes[PRE];
__device__ unsigned            g_bar_cnt;     // self-resetting
__device__ unsigned            g_bar_gen;     // monotone

__device__ __forceinline__ unsigned mono(float f) {
    unsigned b = __float_as_uint(f);
    return (b & 0x80000000u) ? ~b : (b | 0x80000000u);
}
__device__ __forceinline__ float unmono(unsigned m) {
    unsigned b = (m & 0x80000000u) ? (m ^ 0x80000000u) : ~m;
    return __uint_as_float(b);
}
__device__ __forceinline__ float box_area(float4 b) {
    return __fmul_rn(fmaxf(b.z - b.x, 0.0f), fmaxf(b.w - b.y, 0.0f));
}
__device__ __forceinline__ bool iou_gt(float4 a, float areaA, float4 b, float areaB) {
    float lx = fmaxf(a.x, b.x);
    float ly = fmaxf(a.y, b.y);
    float rx = fminf(a.z, b.z);
    float ry = fminf(a.w, b.w);
    float iw = fmaxf(rx - lx, 0.0f);
    float ih = fmaxf(ry - ly, 0.0f);
    float inter = __fmul_rn(iw, ih);
    float uni = fmaxf(__fsub_rn(__fadd_rn(areaA, areaB), inter), 1e-9f);
    return __fdiv_rn(inter, uni) > 0.6f;
}

// software grid barrier — grid <= #SMs and 1 block/SM force wave-1 residency
__device__ __forceinline__ void gsync(int nb) {
    __syncthreads();
    if (threadIdx.x == 0) {
        __threadfence();
        unsigned gen = *((volatile unsigned*)&g_bar_gen);
        unsigned t = atomicAdd(&g_bar_cnt, 1u);
        if (t == (unsigned)(nb - 1)) {
            atomicExch(&g_bar_cnt, 0u);
            __threadfence();
            atomicAdd(&g_bar_gen, 1u);
        } else {
            while (*((volatile unsigned*)&g_bar_gen) == gen) __nanosleep(64);
            __threadfence();
        }
    }
    __syncthreads();
}

__global__ __launch_bounds__(NTHR, 1)
void k_fused(const float* __restrict__ cls,
             const float* __restrict__ deltas,
             const float* __restrict__ anchors,
             float* __restrict__ out, int nb) {
    extern __shared__ char smraw[];
    const int tid = threadIdx.x;
    const int bid = blockIdx.x;
    const int gt  = bid * NTHR + tid;
    const int gs  = nb * NTHR;

    // ---- P1: scores -> 64K-bucket histogram ------------------------------
    for (int i = gt; i < NTOT; i += gs) {
        int k = i / HW;
        int r = i - k * HW;
        float s = __ldg(&cls[(2 * k) * HW + r]);
        atomicAdd(&g_hist[mono(s) >> 16], 1u);
    }
    gsync(nb);

    // ---- P2: boundary bucket of rank PRE (block 0, shfl suffix scan) -----
    if (bid == 0) {
        __shared__ int ws[32];
        const uint4* h4 = (const uint4*)g_hist;
        int base4 = tid * 16;                    // 16 uint4 = 64 buckets
        int sum = 0;
        #pragma unroll
        for (int j = 0; j < 16; ++j) {
            uint4 v = __ldcg(&h4[base4 + j]);
            sum += (int)(v.x + v.y + v.z + v.w);
        }
        int lane = tid & 31, warp = tid >> 5;
        // warp-level inclusive suffix scan (descending)
        int sfx = sum;
        #pragma unroll
        for (int d = 1; d < 32; d <<= 1) {
            int v = __shfl_down_sync(0xFFFFFFFFu, sfx, d);
            if (lane < 32 - d) sfx += v;
        }
        if (lane == 0) ws[warp] = sfx;           // warp total
        __syncthreads();
        int tail = 0;
        for (int w2 = warp + 1; w2 < 32; ++w2) tail += ws[w2];
        int St  = sfx + tail;                    // suffix incl. this thread's 64 buckets
        int Snx = St - sum;                      // suffix excl. (== S_{t+1})
        if (St >= PRE && Snx < PRE) {
            int running = Snx;
            int base = tid * 64;
            int B = base;
            for (int j = 63; j >= 0; --j) {
                running += (int)__ldcg(&g_hist[base + j]);
                if (running >= PRE) { B = base + j; break; }
            }
            g_bound = B;
        }
    }
    gsync(nb);

    // ---- P3: recompute keys, compact candidates >= bound -----------------
    {
        const int bound = __ldcg(&g_bound);
        for (int i = gt; i < NTOT; i += gs) {
            int k = i / HW;
            int r = i - k * HW;
            float s = __ldg(&cls[(2 * k) * HW + r]);
            unsigned key = mono(s);
            if ((int)(key >> 16) >= bound) {
                unsigned pos = atomicAdd(&g_cnt, 1u);
                if (pos < CAP)
                    g_cand[pos] = ((unsigned long long)key << 20)
                                | (unsigned)((~(unsigned)i) & 0xFFFFFu);
            }
        }
    }
    gsync(nb);

    // ---- P4a: exact descending ranks by counting (grid-wide tiles) -------
    {
        unsigned n = __ldcg(&g_cnt);
        if (n > CAP) n = CAP;
        unsigned long long* sk = (unsigned long long*)smraw;
        int csz = ((int)n + CHK - 1) / CHK;
        for (int w = bid; w < GRP * CHK; w += nb) {     // robust if nb < 144
            int g = w / CHK, c = w % CHK;
            int c0 = c * csz;
            int c1 = c0 + csz; if (c1 > (int)n) c1 = (int)n;
            int clen = c1 - c0;
            for (int j = tid; j < clen; j += NTHR) sk[j] = __ldcg(&g_cand[c0 + j]);
            __syncthreads();
            int ci = g * 512 + (tid & 511);
            int h  = tid >> 9;
            if (ci < (int)n && clen > 0) {
                unsigned long long my = __ldcg(&g_cand[ci]);
                int half = (clen + 1) >> 1;
                int j0 = h * half;
                int j1 = j0 + half; if (j1 > clen) j1 = clen;
                int cnt = 0;
                #pragma unroll 8
                for (int j = j0; j < j1; ++j) cnt += (sk[j] > my);
                if (cnt) atomicAdd(&g_rank[ci], (unsigned)cnt);
            }
            __syncthreads();
        }
    }
    gsync(nb);

    // ---- P4b: scatter by rank + box decode/clip (fused gather) ----------
    {
        unsigned n = __ldcg(&g_cnt);
        if (n > CAP) n = CAP;
        for (int i = gt; i < (int)n; i += gs) {
            unsigned r = __ldcg(&g_rank[i]);
            if (r < PRE) {
                unsigned long long cv = __ldcg(&g_cand[i]);
                int idx = (int)((~(unsigned)cv) & 0xFFFFFu);
                g_sc[r] = unmono((unsigned)(cv >> 20));
                int hp = idx / WK;
                int t  = idx - hp * WK;
                int wp = t / KA;
                int kp = t - wp * KA;
                float v[4];
                #pragma unroll
                for (int j = 0; j < 4; ++j) {
                    int F   = ((kp * 4 + j) * HH + hp) * WW + wp;
                    int j2  = F & 3;
                    int F4  = F >> 2;
                    int k2  = F4 % KA;
                    int rem = F4 / KA;
                    int w2  = rem % WW;
                    int h2  = rem / WW;
                    float a = __ldg(&anchors[((h2 * WW + w2) * KA + k2) * 4 + j2]);
                    float d = __ldg(&deltas[(k2 * 4 + j2) * HW + h2 * WW + w2]);
                    v[j] = fminf(fmaxf(a + d, 0.0f), 1920.0f);
                }
                g_boxes[r] = make_float4(v[0], v[1], v[2], v[3]);
            }
        }
    }
    gsync(nb);

    // ---- P6: block-0 lazy batched NMS + output; others restore invariants
    if (bid == 0) {
        float4* bx = (float4*)smraw;             // PRE float4 = 96000 B
        __shared__ float    ar[PRE];
        __shared__ float4   kbox[POST];
        __shared__ float    karea[POST];
        __shared__ int      kidx[POST];
        __shared__ int      s_nk;
        __shared__ unsigned s_sup;

        for (int p = tid; p < PRE; p += NTHR) {
            float4 b = __ldcg(&g_boxes[p]);
            bx[p] = b;
            ar[p] = box_area(b);
        }
        if (tid == 0) { s_nk = 0; s_sup = 0u; }
        __syncthreads();

        for (int base = 0; base < PRE; base += 32) {
            // phase 1: test 32 batch candidates vs all currently-kept boxes
            int nk = s_nk;
            int total = nk << 5;
            for (int idx2 = tid; idx2 < total; idx2 += NTHR) {
                int c = idx2 & 31;
                int j = base + c;
                if (j < PRE && !((s_sup >> c) & 1u)) {     // racy hint: benign, monotone
                    int k = idx2 >> 5;
                    if (iou_gt(kbox[k], karea[k], bx[j], ar[j]))
                        atomicOr(&s_sup, 1u << c);
                }
            }
            __syncthreads();

            // phase 2: one warp serially resolves survivors within the batch
            if (tid < 32) {
                int lane = tid;
                int rem  = PRE - base;
                unsigned valid = (rem >= 32) ? 0xFFFFFFFFu : ((1u << rem) - 1u);
                unsigned alive = (~s_sup) & valid;
                int myj = base + ((lane < rem) ? lane : 0);
                float4 myb = bx[myj];
                float  mya = ar[myj];
                int nk2 = s_nk;
                while (alive && nk2 < POST) {
                    int l = __ffs((int)alive) - 1;
                    alive &= ~(1u << l);
                    float4 kb;
                    kb.x = __shfl_sync(0xFFFFFFFFu, myb.x, l);
                    kb.y = __shfl_sync(0xFFFFFFFFu, myb.y, l);
                    kb.z = __shfl_sync(0xFFFFFFFFu, myb.z, l);
                    kb.w = __shfl_sync(0xFFFFFFFFu, myb.w, l);
                    float ka_ = __shfl_sync(0xFFFFFFFFu, mya, l);
                    if (lane == 0) { kbox[nk2] = kb; karea[nk2] = ka_; kidx[nk2] = base + l; }
                    ++nk2;
                    if (nk2 >= POST) break;
                    bool sup = false;
                    if (alive & (1u << lane)) sup = iou_gt(kb, ka_, myb, mya);
                    alive &= ~__ballot_sync(0xFFFFFFFFu, sup);
                }
                if (lane == 0) { s_nk = nk2; s_sup = 0u; }
            }
            __syncthreads();
            if (s_nk >= POST) break;
        }

        int nk = s_nk;
        for (int p = tid; p < POST; p += NTHR) {
            int q = (p < nk) ? kidx[p] : 0;
            float4 b = bx[q];
            out[p * 5 + 0] = g_sc[q];
            out[p * 5 + 1] = b.x;
            out[p * 5 + 2] = b.y;
            out[p * 5 + 3] = b.z;
            out[p * 5 + 4] = b.w;
        }
    } else {
        // restore zero invariants for the next launch (dead data now)
        int gt2 = (bid - 1) * NTHR + tid;
        int gs2 = (nb - 1) * NTHR;
        for (int i = gt2; i < NB;  i += gs2) g_hist[i] = 0u;
        for (int i = gt2; i < CAP; i += gs2) g_rank[i] = 0u;
        if (bid == 1 && tid == 0) g_cnt = 0u;
    }
}

// ---------------------------------------------------------------- launcher
extern "C" void kernel_launch(void* const* d_in, const int* in_sizes, int n_in,
                              void* d_out, int out_size) {
    const float* cls     = (const float*)d_in[0];  // [1, 2K, H, W]
    const float* deltas  = (const float*)d_in[1];  // [1, 4K, H, W]
    const float* anchors = (const float*)d_in[2];  // [H, W, K, 4]
    float* out = (float*)d_out;                    // [1, POST, 5]

    int smCount = MAXBLK;
    cudaDeviceGetAttribute(&smCount, cudaDevAttrMultiProcessorCount, 0);
    int nb = smCount < MAXBLK ? smCount : MAXBLK;

    size_t dsz = (size_t)PRE * sizeof(float4);     // 96000 B dynamic

    cudaFuncSetAttribute(k_fused, cudaFuncAttributeMaxDynamicSharedMemorySize, (int)dsz);
    k_fused<<<nb, NTHR, dsz>>>(cls, deltas, anchors, out, nb);
}

// round 7
// speedup vs baseline: 6.6071x; 1.5811x over previous
#include <cuda_runtime.h>

#define KA    9
#define HH    240
#define WW    240
#define HW    57600
#define NTOT  518400
#define WK    2160
#define PRE   6000
#define POST  300
#define CAP   8192
#define NB    65536
#define CHK   9
#define MROW  2048            // matrix-covered candidates
#define MW    64              // words per row

__device__ unsigned            g_hist[NB];    // zero invariant
__device__ unsigned            g_cnt;         // zero invariant
__device__ unsigned            g_rank[CAP];   // zero invariant
__device__ int                 g_bound;
__device__ unsigned long long  g_cand[CAP];
__device__ float               g_sc[PRE];
__device__ float4              g_boxes[PRE];
__device__ unsigned            g_mat[MROW * MW];

__device__ __forceinline__ unsigned mono(float f) {
    unsigned b = __float_as_uint(f);
    return (b & 0x80000000u) ? ~b : (b | 0x80000000u);
}
__device__ __forceinline__ float unmono(unsigned m) {
    unsigned b = (m & 0x80000000u) ? (m ^ 0x80000000u) : ~m;
    return __uint_as_float(b);
}
__device__ __forceinline__ float box_area(float4 b) {
    return __fmul_rn(fmaxf(b.z - b.x, 0.0f), fmaxf(b.w - b.y, 0.0f));
}
__device__ __forceinline__ bool iou_gt(float4 a, float areaA, float4 b, float areaB) {
    float lx = fmaxf(a.x, b.x);
    float ly = fmaxf(a.y, b.y);
    float rx = fminf(a.z, b.z);
    float ry = fminf(a.w, b.w);
    float iw = fmaxf(rx - lx, 0.0f);
    float ih = fmaxf(ry - ly, 0.0f);
    float inter = __fmul_rn(iw, ih);
    float uni = fmaxf(__fsub_rn(__fadd_rn(areaA, areaB), inter), 1e-9f);
    return __fdiv_rn(inter, uni) > 0.6f;
}

// ---- 1: scores -> 64K-bucket histogram ----------------------------------
__global__ void k_hist(const float* __restrict__ cls) {
    int i = blockIdx.x * blockDim.x + threadIdx.x;
    if (i >= NTOT) return;
    int k = i / HW;
    int r = i - k * HW;
    float s = __ldg(&cls[(2 * k) * HW + r]);
    atomicAdd(&g_hist[mono(s) >> 16], 1u);
}

// ---- 2: boundary bucket of rank PRE -------------------------------------
__global__ __launch_bounds__(1024) void k_bound() {
    __shared__ int ws[32];
    int tid = threadIdx.x;
    const uint4* h4 = (const uint4*)g_hist;
    int base4 = tid * 16;
    int sum = 0;
    #pragma unroll
    for (int j = 0; j < 16; ++j) {
        uint4 v = h4[base4 + j];
        sum += (int)(v.x + v.y + v.z + v.w);
    }
    int lane = tid & 31, warp = tid >> 5;
    int sfx = sum;
    #pragma unroll
    for (int d = 1; d < 32; d <<= 1) {
        int v = __shfl_down_sync(0xFFFFFFFFu, sfx, d);
        if (lane < 32 - d) sfx += v;
    }
    if (lane == 0) ws[warp] = sfx;
    __syncthreads();
    int tail = 0;
    for (int w2 = warp + 1; w2 < 32; ++w2) tail += ws[w2];
    int St  = sfx + tail;
    int Snx = St - sum;
    if (St >= PRE && Snx < PRE) {
        int running = Snx;
        int base = tid * 64;
        int B = base;
        for (int j = 63; j >= 0; --j) {
            running += (int)g_hist[base + j];
            if (running >= PRE) { B = base + j; break; }
        }
        g_bound = B;
    }
}

// ---- 3: compact candidates >= bound -------------------------------------
__global__ void k_compact(const float* __restrict__ cls) {
    int i = blockIdx.x * blockDim.x + threadIdx.x;
    if (i >= NTOT) return;
    int k = i / HW;
    int r = i - k * HW;
    float s = __ldg(&cls[(2 * k) * HW + r]);
    unsigned key = mono(s);
    if ((int)(key >> 16) >= g_bound) {
        unsigned pos = atomicAdd(&g_cnt, 1u);
        if (pos < CAP)
            g_cand[pos] = ((unsigned long long)key << 20)
                        | (unsigned)((~(unsigned)i) & 0xFFFFFu);
    }
}

// ---- 4: exact descending ranks by counting (144 tile blocks) ------------
__global__ __launch_bounds__(1024) void k_rank() {
    __shared__ unsigned long long sk[1024];
    unsigned n = g_cnt; if (n > CAP) n = CAP;
    int csz = ((int)n + CHK - 1) / CHK;            // <= 911
    int w = blockIdx.x;                            // 0..143
    int g = w / CHK, c = w % CHK;
    int c0 = c * csz;
    int c1 = c0 + csz; if (c1 > (int)n) c1 = (int)n;
    int clen = c1 - c0;
    for (int j = threadIdx.x; j < clen; j += 1024) sk[j] = g_cand[c0 + j];
    __syncthreads();
    int ci = g * 512 + (threadIdx.x & 511);
    int h  = threadIdx.x >> 9;
    if (ci < (int)n && clen > 0) {
        unsigned long long my = g_cand[ci];
        int half = (clen + 1) >> 1;
        int j0 = h * half;
        int j1 = j0 + half; if (j1 > clen) j1 = clen;
        int cnt = 0;
        #pragma unroll 8
        for (int j = j0; j < j1; ++j) cnt += (sk[j] > my);
        if (cnt) atomicAdd(&g_rank[ci], (unsigned)cnt);
    }
}

// ---- 5: scatter by rank + box decode/clip -------------------------------
__global__ void k_scatter(const float* __restrict__ deltas,
                          const float* __restrict__ anchors) {
    int i = blockIdx.x * blockDim.x + threadIdx.x;
    unsigned n = g_cnt; if (n > CAP) n = CAP;
    if (i >= (int)n) return;
    unsigned r = g_rank[i];
    if (r >= PRE) return;
    unsigned long long cv = g_cand[i];
    int idx = (int)((~(unsigned)cv) & 0xFFFFFu);
    g_sc[r] = unmono((unsigned)(cv >> 20));
    int hp = idx / WK;
    int t  = idx - hp * WK;
    int wp = t / KA;
    int kp = t - wp * KA;
    float v[4];
    #pragma unroll
    for (int j = 0; j < 4; ++j) {
        int F   = ((kp * 4 + j) * HH + hp) * WW + wp;
        int j2  = F & 3;
        int F4  = F >> 2;
        int k2  = F4 % KA;
        int rem = F4 / KA;
        int w2  = rem % WW;
        int h2  = rem / WW;
        float a = __ldg(&anchors[((h2 * WW + w2) * KA + k2) * 4 + j2]);
        float d = __ldg(&deltas[(k2 * 4 + j2) * HW + h2 * WW + w2]);
        v[j] = fminf(fmaxf(a + d, 0.0f), 1920.0f);
    }
    g_boxes[r] = make_float4(v[0], v[1], v[2], v[3]);
}

// ---- 6: suppression bit-matrix among top MROW candidates ----------------
// row i, word w, bit l: IoU(box_i, box_{32w+l}) > 0.6. Bits j<=i harmless.
__global__ __launch_bounds__(1024) void k_mat() {
    int i = blockIdx.x;
    float4 bi = g_boxes[i];
    float  ai = box_area(bi);
    int j0 = threadIdx.x;
    int j1 = j0 + 1024;
    float4 b0 = g_boxes[j0];
    float4 b1 = g_boxes[j1];
    bool s0 = iou_gt(bi, ai, b0, box_area(b0));
    bool s1 = iou_gt(bi, ai, b1, box_area(b1));
    unsigned w0 = __ballot_sync(0xFFFFFFFFu, s0);
    unsigned w1 = __ballot_sync(0xFFFFFFFFu, s1);
    int w = j0 >> 5;
    if ((j0 & 31) == 0) {
        g_mat[i * MW + w]      = w0;
        g_mat[i * MW + w + 32] = w1;
    }
}

// ---- 7: warp-serial matrix sweep + fallback + output --------------------
__global__ __launch_bounds__(1024) void k_nms(float* __restrict__ out) {
    __shared__ unsigned rowbuf[32 * MW];          // 8 KB: one chunk of rows
    __shared__ int      s_kidx[POST];
    __shared__ int      s_nk;
    __shared__ float4   kbox[POST];               // fallback kept cache
    __shared__ float    karea[POST];
    __shared__ float4   bb[32];                   // fallback batch boxes
    __shared__ float    ba[32];
    __shared__ unsigned s_sup;
    int tid = threadIdx.x, lane = tid & 31, warp = tid >> 5;

    if (warp == 0) {
        unsigned m0 = 0u, m1 = 0u;                // lane owns mask words 2*lane, 2*lane+1
        int nk = 0;
        for (int c = 0; c < MW && nk < POST; ++c) {
            // prefetch chunk rows: g_mat[32c .. 32c+31] = 2048 contiguous words
            const uint4* src = (const uint4*)&g_mat[(c << 5) * MW];
            uint4* dst = (uint4*)rowbuf;
            #pragma unroll
            for (int q = 0; q < 16; ++q) dst[lane + 32 * q] = __ldcg(&src[lane + 32 * q]);
            __syncwarp();
            unsigned wc = __shfl_sync(0xFFFFFFFFu, (c & 1) ? m1 : m0, c >> 1);
            unsigned alive = ~wc;
            while (alive && nk < POST) {
                int l = __ffs(alive) - 1;
                if (lane == 0) s_kidx[nk] = (c << 5) + l;
                ++nk;
                m0 |= rowbuf[l * MW + 2 * lane];
                m1 |= rowbuf[l * MW + 2 * lane + 1];
                unsigned wcn = __shfl_sync(0xFFFFFFFFu, (c & 1) ? m1 : m0, c >> 1);
                alive = (~wcn) & ~((2u << l) - 1u);   // unsuppressed, index > l
            }
            __syncwarp();
        }
        if (lane == 0) s_nk = nk;
    }
    __syncthreads();
    int nk = s_nk;

    // fallback: continue past MROW with lazy batches (rarely taken)
    if (nk < POST) {
        for (int p = tid; p < nk; p += 1024) {
            float4 b = g_boxes[s_kidx[p]];
            kbox[p] = b; karea[p] = box_area(b);
        }
        if (tid == 0) s_sup = 0u;
        __syncthreads();
        for (int base = MROW; base < PRE && nk < POST; base += 32) {
            int rem = PRE - base; if (rem > 32) rem = 32;
            if (tid < rem) {
                float4 b = g_boxes[base + tid];
                bb[tid] = b; ba[tid] = box_area(b);
            }
            __syncthreads();
            int total = nk << 5;
            for (int idx2 = tid; idx2 < total; idx2 += 1024) {
                int cc = idx2 & 31;
                if (cc < rem && !((s_sup >> cc) & 1u)) {
                    int k = idx2 >> 5;
                    if (iou_gt(kbox[k], karea[k], bb[cc], ba[cc]))
                        atomicOr(&s_sup, 1u << cc);
                }
            }
            __syncthreads();
            if (tid < 32) {
                unsigned valid = (rem >= 32) ? 0xFFFFFFFFu : ((1u << rem) - 1u);
                unsigned alive = (~s_sup) & valid;
                float4 myb = bb[(lane < rem) ? lane : 0];
                float  mya = ba[(lane < rem) ? lane : 0];
                int nk2 = nk;
                while (alive && nk2 < POST) {
                    int l = __ffs((int)alive) - 1;
                    alive &= ~(1u << l);
                    float4 kb;
                    kb.x = __shfl_sync(0xFFFFFFFFu, myb.x, l);
                    kb.y = __shfl_sync(0xFFFFFFFFu, myb.y, l);
                    kb.z = __shfl_sync(0xFFFFFFFFu, myb.z, l);
                    kb.w = __shfl_sync(0xFFFFFFFFu, myb.w, l);
                    float ka_ = __shfl_sync(0xFFFFFFFFu, mya, l);
                    if (lane == 0) { kbox[nk2] = kb; karea[nk2] = ka_; s_kidx[nk2] = base + l; }
                    ++nk2;
                    if (nk2 >= POST) break;
                    bool sup = false;
                    if (alive & (1u << lane)) sup = iou_gt(kb, ka_, myb, mya);
                    alive &= ~__ballot_sync(0xFFFFFFFFu, sup);
                }
                if (lane == 0) { s_nk = nk2; s_sup = 0u; }
            }
            __syncthreads();
            nk = s_nk;
        }
    }

    // output [1, POST, 5]; pad with candidate 0 (nonzero fill_value=0)
    for (int p = tid; p < POST; p += 1024) {
        int q = (p < nk) ? s_kidx[p] : 0;
        float4 b = g_boxes[q];
        out[p * 5 + 0] = g_sc[q];
        out[p * 5 + 1] = b.x;
        out[p * 5 + 2] = b.y;
        out[p * 5 + 3] = b.z;
        out[p * 5 + 4] = b.w;
    }
}

// ---- 8: restore zero invariants for next launch -------------------------
__global__ void k_reset() {
    int i = blockIdx.x * blockDim.x + threadIdx.x;
    if (i < NB)  g_hist[i] = 0u;
    if (i < CAP) g_rank[i] = 0u;
    if (i == 0)  g_cnt = 0u;
}

// ---------------------------------------------------------------- launcher
extern "C" void kernel_launch(void* const* d_in, const int* in_sizes, int n_in,
                              void* d_out, int out_size) {
    const float* cls     = (const float*)d_in[0];
    const float* deltas  = (const float*)d_in[1];
    const float* anchors = (const float*)d_in[2];
    float* out = (float*)d_out;

    k_hist   <<<(NTOT + 255) / 256, 256>>>(cls);
    k_bound  <<<1, 1024>>>();
    k_compact<<<(NTOT + 255) / 256, 256>>>(cls);
    k_rank   <<<144, 1024>>>();
    k_scatter<<<(CAP + 255) / 256, 256>>>(deltas, anchors);
    k_mat    <<<MROW, 1024>>>();
    k_nms    <<<1, 1024>>>(out);
    k_reset  <<<(NB + 255) / 256, 256>>>();
}